// round 13
// baseline (speedup 1.0000x reference)
#include <cuda_runtime.h>
#include <cuda_bf16.h>
#include <cstdint>

// Problem constants
#define B_      32
#define NHEAD   32
#define NKV     8
#define NREP    4
#define HDIM    128
#define HIDDEN_ 4096
#define QKV_OUT_ 6144          // (8*2+32)*128
#define QD      4096           // NHEAD*HDIM
#define KD      1024           // NKV*HDIM
#define PAST    2048
#define T_TOT   2049           // PAST + 1
#define SCALE_  0.08838834764831845f  // 1/sqrt(128)

// d_out layout: [out (32*32*128)] [k_cat (32*2049*8*128)] [v_cat (...)]
#define OFF_OUT 0
#define SZ_OUT  (B_*NHEAD*HDIM)
#define OFF_K   (SZ_OUT)
#define SZ_KC   ((size_t)B_*T_TOT*NKV*HDIM)
#define OFF_V   (OFF_K + SZ_KC)

// GEMM split-K
#define KSPLIT  8
#define KPER    (HIDDEN_/KSPLIT)                // 512
#define KCH     32
#define NTILE   128
#define XSTR    40

// attention chunking
#define TCHUNK  256
#define NCHUNK  9                                // chunks 0..7 = past, chunk 8 = new token

// ---------------- scratch ----------------
__device__ float g_part[KSPLIT * B_ * QKV_OUT_];
__device__ float g_q[B_ * QD];
__device__ float g_pm[B_ * NKV * NCHUNK * NREP];
__device__ float g_pl[B_ * NKV * NCHUNK * NREP];
__device__ float g_pacc[B_ * NKV * NCHUNK * NREP * HDIM];

// ---------------- tensor-core helpers ----------------
__device__ __forceinline__ uint32_t smem_u32(const void* p) {
    return (uint32_t)__cvta_generic_to_shared(p);
}

__device__ __forceinline__ void ldsm4(uint32_t* r, uint32_t addr) {
    asm volatile("ldmatrix.sync.aligned.m8n8.x4.shared.b16 {%0,%1,%2,%3}, [%4];\n"
                 : "=r"(r[0]), "=r"(r[1]), "=r"(r[2]), "=r"(r[3]) : "r"(addr));
}

__device__ __forceinline__ void mma_bf16(float* d, const uint32_t* a, const uint32_t* b) {
    asm volatile(
        "mma.sync.aligned.m16n8k16.row.col.f32.bf16.bf16.f32 "
        "{%0,%1,%2,%3}, {%4,%5,%6,%7}, {%8,%9}, {%0,%1,%2,%3};\n"
        : "+f"(d[0]), "+f"(d[1]), "+f"(d[2]), "+f"(d[3])
        : "r"(a[0]), "r"(a[1]), "r"(a[2]), "r"(a[3]), "r"(b[0]), "r"(b[1]));
}

__device__ __forceinline__ void cvt_hilo(float x, __nv_bfloat16& h, __nv_bfloat16& l) {
    h = __float2bfloat16(x);
    l = __float2bfloat16(x - __bfloat162float(h));
}

// ---------------- Kernel 1: QKV GEMM (bf16 hi/lo, register-prefetched mainloop) ----------------
__global__ __launch_bounds__(256) void gemm_kernel(
    const float* __restrict__ X, const float* __restrict__ W)
{
    __shared__ __nv_bfloat16 Xh[32][XSTR], Xl[32][XSTR];
    __shared__ __nv_bfloat16 Wh[NTILE][XSTR], Wl[NTILE][XSTR];

    const int tid = threadIdx.x;
    const int warp = tid >> 5, lane = tid & 31;
    const int wm = warp & 1, wn = warp >> 1;
    const int o0 = blockIdx.x * NTILE;
    const int k0 = blockIdx.y * KPER;

    float d[4][4];
#pragma unroll
    for (int i = 0; i < 4; i++)
#pragma unroll
        for (int j = 0; j < 4; j++) d[i][j] = 0.f;

    const int a_row = wm * 16 + (lane & 7) + ((lane & 8) ? 8 : 0);
    const int a_ks  = (lane & 16) ? 8 : 0;
    const int b_row0 = wn * 32 + (lane & 7) + ((lane & 16) ? 8 : 0);
    const int b_ks  = (lane & 8) ? 8 : 0;

    // per-thread load coordinates
    const int xr = tid >> 3, xc4 = (tid & 7) * 4;
    const int wo = tid >> 1, wbase = (tid & 1) * 16;
    const float* Xp = &X[(size_t)xr * HIDDEN_ + k0 + xc4];
    const float* Wp = &W[(size_t)(o0 + wo) * HIDDEN_ + k0 + wbase];

    // prologue: fetch tile 0 into registers
    float4 xv = *(const float4*)Xp;
    float4 wv[4];
#pragma unroll
    for (int i = 0; i < 4; i++) wv[i] = ((const float4*)Wp)[i];

    for (int kc = 0; kc < KPER; kc += KCH) {
        // convert current registers -> smem
        cvt_hilo(xv.x, Xh[xr][xc4+0], Xl[xr][xc4+0]);
        cvt_hilo(xv.y, Xh[xr][xc4+1], Xl[xr][xc4+1]);
        cvt_hilo(xv.z, Xh[xr][xc4+2], Xl[xr][xc4+2]);
        cvt_hilo(xv.w, Xh[xr][xc4+3], Xl[xr][xc4+3]);
#pragma unroll
        for (int i = 0; i < 4; i++) {
            int kk = wbase + i * 4;
            cvt_hilo(wv[i].x, Wh[wo][kk+0], Wl[wo][kk+0]);
            cvt_hilo(wv[i].y, Wh[wo][kk+1], Wl[wo][kk+1]);
            cvt_hilo(wv[i].z, Wh[wo][kk+2], Wl[wo][kk+2]);
            cvt_hilo(wv[i].w, Wh[wo][kk+3], Wl[wo][kk+3]);
        }
        __syncthreads();

        // prefetch next tile into registers (overlaps with ldsm+mma below)
        {
            int kn = (kc + KCH < KPER) ? (kc + KCH) : kc;
            xv = *(const float4*)(Xp + kn);
#pragma unroll
            for (int i = 0; i < 4; i++) wv[i] = ((const float4*)(Wp + kn))[i];
        }

#pragma unroll
        for (int ks = 0; ks < 2; ks++) {
            const int kk = ks * 16;
            uint32_t ah[4], al[4];
            ldsm4(ah, smem_u32(&Xh[a_row][kk + a_ks]));
            ldsm4(al, smem_u32(&Xl[a_row][kk + a_ks]));
            uint32_t bh[8], bl[8];
            ldsm4(bh + 0, smem_u32(&Wh[b_row0][kk + b_ks]));
            ldsm4(bh + 4, smem_u32(&Wh[b_row0 + 16][kk + b_ks]));
            ldsm4(bl + 0, smem_u32(&Wl[b_row0][kk + b_ks]));
            ldsm4(bl + 4, smem_u32(&Wl[b_row0 + 16][kk + b_ks]));
#pragma unroll
            for (int nt = 0; nt < 4; nt++) {
                uint32_t* Bh = bh + nt * 2;
                uint32_t* Bl = bl + nt * 2;
                mma_bf16(d[nt], ah, Bh);
                mma_bf16(d[nt], ah, Bl);
                mma_bf16(d[nt], al, Bh);
            }
        }
        __syncthreads();
    }

    const int g = lane >> 2, t2 = (lane & 3) * 2;
    const int ksb = blockIdx.y * B_;
#pragma unroll
    for (int nt = 0; nt < 4; nt++) {
        int o = o0 + wn * 32 + nt * 8 + t2;
        int b0 = wm * 16 + g;
        float* dst0 = &g_part[(size_t)(ksb + b0) * QKV_OUT_ + o];
        dst0[0] = d[nt][0]; dst0[1] = d[nt][1];
        float* dst1 = &g_part[(size_t)(ksb + b0 + 8) * QKV_OUT_ + o];
        dst1[0] = d[nt][2]; dst1[1] = d[nt][3];
    }
}

// ---------------- Kernel 2: split-K reduce + bias + scatter ----------------
__global__ __launch_bounds__(256) void gemm_reduce_kernel(
    const float* __restrict__ bias, float* __restrict__ out)
{
    int i = blockIdx.x * 256 + threadIdx.x;
    if (i >= B_ * QKV_OUT_) return;
    int b = i / QKV_OUT_, o = i - b * QKV_OUT_;
    float s = bias[o];
#pragma unroll
    for (int ks = 0; ks < KSPLIT; ks++)
        s += g_part[(size_t)(ks * B_ + b) * QKV_OUT_ + o];
    if (o < QD) {
        g_q[b * QD + o] = s;
    } else if (o < QD + KD) {
        int r = o - QD;
        out[OFF_K + ((size_t)b * T_TOT + PAST) * KD + r] = s;
    } else {
        int r = o - QD - KD;
        out[OFF_V + ((size_t)b * T_TOT + PAST) * KD + r] = s;
    }
}

// ---------------- Kernel 3: fused cache-copy + split-KV flash attention ----------------
// Chunks 0..7: branch-free hot loop, 4 tokens/iter (MLP=8), streaming hints.
// Chunk 8: single new token (t=2048), warp 0 only.
__global__ __launch_bounds__(256) void attn_kernel(
    const float* __restrict__ Kc, const float* __restrict__ Vc,
    const float* __restrict__ mask, float* __restrict__ out)
{
    const int ch = blockIdx.x, kv = blockIdx.y, b = blockIdx.z;
    const int w = threadIdx.x >> 5, lane = threadIdx.x & 31;

    float4 q[NREP];
#pragma unroll
    for (int h = 0; h < NREP; h++)
        q[h] = *(const float4*)&g_q[(size_t)b * QD + (kv * NREP + h) * HDIM + lane * 4];

    float m[NREP], l[NREP];
    float4 acc[NREP];
#pragma unroll
    for (int h = 0; h < NREP; h++) {
        m[h] = -1e30f; l[h] = 0.f;
        acc[h] = make_float4(0.f, 0.f, 0.f, 0.f);
    }

    if (ch < 8) {
        const int t0 = ch * TCHUNK + w * 32;
        const size_t sstride = (size_t)NKV * HDIM;   // token stride (src)
        const size_t dstride = (size_t)NKV * HDIM;   // token stride (dst) — same inner layout
#pragma unroll 1
        for (int j = 0; j < 32; j += 4) {
            const int t = t0 + j;
            const size_t s0 = (((size_t)b * PAST + t) * NKV + kv) * HDIM;
            const size_t d0 = (((size_t)b * T_TOT + t) * NKV + kv) * HDIM;

            // ---- 8 loads up front (MLP=8) ----
            float4 k4[4], v4[4];
#pragma unroll
            for (int i = 0; i < 4; i++) {
                k4[i] = __ldcs(((const float4*)(Kc + s0 + i * sstride)) + lane);
                v4[i] = __ldcs(((const float4*)(Vc + s0 + i * sstride)) + lane);
            }
            float mk[4];
#pragma unroll
            for (int i = 0; i < 4; i++)
                mk[i] = __ldg(&mask[(size_t)b * T_TOT + t + i]);

            // ---- fused cache copy (streaming) ----
#pragma unroll
            for (int i = 0; i < 4; i++) {
                __stcs(((float4*)(out + OFF_K + d0 + i * dstride)) + lane, k4[i]);
                __stcs(((float4*)(out + OFF_V + d0 + i * dstride)) + lane, v4[i]);
            }

            // ---- scores: 4 heads x 4 tokens ----
            float s[NREP][4];
#pragma unroll
            for (int h = 0; h < NREP; h++)
#pragma unroll
                for (int i = 0; i < 4; i++)
                    s[h][i] = q[h].x * k4[i].x + q[h].y * k4[i].y
                            + q[h].z * k4[i].z + q[h].w * k4[i].w;
#pragma unroll
            for (int off = 16; off; off >>= 1)
#pragma unroll
                for (int h = 0; h < NREP; h++)
#pragma unroll
                    for (int i = 0; i < 4; i++)
                        s[h][i] += __shfl_xor_sync(0xFFFFFFFFu, s[h][i], off);

            // ---- 4-token online-softmax update ----
#pragma unroll
            for (int h = 0; h < NREP; h++) {
                float sv0 = s[h][0] * SCALE_ + mk[0];
                float sv1 = s[h][1] * SCALE_ + mk[1];
                float sv2 = s[h][2] * SCALE_ + mk[2];
                float sv3 = s[h][3] * SCALE_ + mk[3];
                float mn = fmaxf(fmaxf(fmaxf(sv0, sv1), fmaxf(sv2, sv3)), m[h]);
                float corr = __expf(m[h] - mn);
                float p0 = __expf(sv0 - mn);
                float p1 = __expf(sv1 - mn);
                float p2 = __expf(sv2 - mn);
                float p3 = __expf(sv3 - mn);
                l[h] = l[h] * corr + ((p0 + p1) + (p2 + p3));
                acc[h].x = acc[h].x * corr + p0*v4[0].x + p1*v4[1].x + p2*v4[2].x + p3*v4[3].x;
                acc[h].y = acc[h].y * corr + p0*v4[0].y + p1*v4[1].y + p2*v4[2].y + p3*v4[3].y;
                acc[h].z = acc[h].z * corr + p0*v4[0].z + p1*v4[1].z + p2*v4[2].z + p3*v4[3].z;
                acc[h].w = acc[h].w * corr + p0*v4[0].w + p1*v4[1].w + p2*v4[2].w + p3*v4[3].w;
                m[h] = mn;
            }
        }
    } else if (w == 0) {
        // single new token t = PAST (written to out by gemm_reduce)
        const int t = PAST;
        const size_t d0 = (((size_t)b * T_TOT + t) * NKV + kv) * HDIM;
        float4 k4 = __ldg(((const float4*)(out + OFF_K + d0)) + lane);
        float4 v4 = __ldg(((const float4*)(out + OFF_V + d0)) + lane);
        float mk = __ldg(&mask[(size_t)b * T_TOT + t]);
        float s[NREP];
#pragma unroll
        for (int h = 0; h < NREP; h++)
            s[h] = q[h].x * k4.x + q[h].y * k4.y + q[h].z * k4.z + q[h].w * k4.w;
#pragma unroll
        for (int off = 16; off; off >>= 1)
#pragma unroll
            for (int h = 0; h < NREP; h++)
                s[h] += __shfl_xor_sync(0xFFFFFFFFu, s[h], off);
#pragma unroll
        for (int h = 0; h < NREP; h++) {
            float sv = s[h] * SCALE_ + mk;
            m[h] = sv; l[h] = 1.f;
            acc[h] = make_float4(v4.x, v4.y, v4.z, v4.w);
        }
    }

    __shared__ float sm_m[8][NREP];
    __shared__ float sm_l[8][NREP];
    __shared__ float sm_acc[8][NREP][HDIM];
    if (lane < NREP) { sm_m[w][lane] = m[lane]; sm_l[w][lane] = l[lane]; }
#pragma unroll
    for (int h = 0; h < NREP; h++)
        *(float4*)&sm_acc[w][h][lane * 4] = acc[h];
    __syncthreads();

    const int base = ((b * NKV + kv) * NCHUNK + ch) * NREP;
    for (int e = threadIdx.x; e < NREP * HDIM; e += 256) {
        int h = e >> 7, dd = e & 127;
        float M = sm_m[0][h];
#pragma unroll
        for (int ww = 1; ww < 8; ww++) M = fmaxf(M, sm_m[ww][h]);
        float a = 0.f;
#pragma unroll
        for (int ww = 0; ww < 8; ww++)
            a += sm_acc[ww][h][dd] * __expf(sm_m[ww][h] - M);
        g_pacc[(size_t)(base + h) * HDIM + dd] = a;
    }
    if (threadIdx.x < NREP) {
        int h = threadIdx.x;
        float M = sm_m[0][h];
#pragma unroll
        for (int ww = 1; ww < 8; ww++) M = fmaxf(M, sm_m[ww][h]);
        float L = 0.f;
#pragma unroll
        for (int ww = 0; ww < 8; ww++)
            L += sm_l[ww][h] * __expf(sm_m[ww][h] - M);
        g_pm[base + h] = M;
        g_pl[base + h] = L;
    }
}

// ---------------- Kernel 4: cross-chunk softmax reduce ----------------
__global__ __launch_bounds__(128) void attn_final_kernel(float* __restrict__ out)
{
    const int h = blockIdx.x, b = blockIdx.y, d = threadIdx.x;
    const int kv = h >> 2, hh = h & 3;
    const int base0 = (b * NKV + kv) * NCHUNK;
    float M = -1e30f;
#pragma unroll
    for (int ch = 0; ch < NCHUNK; ch++)
        M = fmaxf(M, g_pm[(base0 + ch) * NREP + hh]);
    float L = 0.f, A = 0.f;
#pragma unroll
    for (int ch = 0; ch < NCHUNK; ch++) {
        int idx = (base0 + ch) * NREP + hh;
        float f = __expf(g_pm[idx] - M);
        L += g_pl[idx] * f;
        A += g_pacc[(size_t)idx * HDIM + d] * f;
    }
    out[OFF_OUT + ((size_t)b * NHEAD + h) * HDIM + d] = A / L;
}

// ---------------- launch ----------------
extern "C" void kernel_launch(void* const* d_in, const int* in_sizes, int n_in,
                              void* d_out, int out_size)
{
    const float* input_t = (const float*)d_in[0];
    const float* key_cache = (const float*)d_in[1];
    const float* value_cache = (const float*)d_in[2];
    const float* attention_mask = (const float*)d_in[4];
    const float* W_qkv = (const float*)d_in[6];
    const float* b_qkv = (const float*)d_in[7];
    float* out = (float*)d_out;

    gemm_kernel<<<dim3(QKV_OUT_ / NTILE, KSPLIT), 256>>>(input_t, W_qkv);
    gemm_reduce_kernel<<<(B_ * QKV_OUT_ + 255) / 256, 256>>>(b_qkv, out);
    attn_kernel<<<dim3(NCHUNK, NKV, B_), 256>>>(key_cache, value_cache, attention_mask, out);
    attn_final_kernel<<<dim3(NHEAD, B_), 128>>>(out);
}

// round 14
// speedup vs baseline: 1.0413x; 1.0413x over previous
#include <cuda_runtime.h>
#include <cuda_bf16.h>
#include <cstdint>

// Problem constants
#define B_      32
#define NHEAD   32
#define NKV     8
#define NREP    4
#define HDIM    128
#define HIDDEN_ 4096
#define QKV_OUT_ 6144          // (8*2+32)*128
#define QD      4096           // NHEAD*HDIM
#define KD      1024           // NKV*HDIM
#define PAST    2048
#define T_TOT   2049           // PAST + 1
#define SCALE_  0.08838834764831845f  // 1/sqrt(128)

// d_out layout: [out (32*32*128)] [k_cat (32*2049*8*128)] [v_cat (...)]
#define OFF_OUT 0
#define SZ_OUT  (B_*NHEAD*HDIM)
#define OFF_K   (SZ_OUT)
#define SZ_KC   ((size_t)B_*T_TOT*NKV*HDIM)
#define OFF_V   (OFF_K + SZ_KC)

// GEMM split-K
#define KSPLIT  8
#define KPER    (HIDDEN_/KSPLIT)                // 512
#define KCH     32
#define NTILE   128
#define XSTR    40

// attention chunking
#define TCHUNK  256
#define NCHUNK  9                                // chunks 0..7 = past, chunk 8 = new token

// ---------------- scratch ----------------
__device__ float g_part[KSPLIT * B_ * QKV_OUT_];
__device__ float g_q[B_ * QD];
__device__ float g_pm[B_ * NKV * NCHUNK * NREP];
__device__ float g_pl[B_ * NKV * NCHUNK * NREP];
__device__ float g_pacc[B_ * NKV * NCHUNK * NREP * HDIM];

// ---------------- tensor-core helpers ----------------
__device__ __forceinline__ uint32_t smem_u32(const void* p) {
    return (uint32_t)__cvta_generic_to_shared(p);
}

__device__ __forceinline__ void ldsm4(uint32_t* r, uint32_t addr) {
    asm volatile("ldmatrix.sync.aligned.m8n8.x4.shared.b16 {%0,%1,%2,%3}, [%4];\n"
                 : "=r"(r[0]), "=r"(r[1]), "=r"(r[2]), "=r"(r[3]) : "r"(addr));
}

__device__ __forceinline__ void mma_bf16(float* d, const uint32_t* a, const uint32_t* b) {
    asm volatile(
        "mma.sync.aligned.m16n8k16.row.col.f32.bf16.bf16.f32 "
        "{%0,%1,%2,%3}, {%4,%5,%6,%7}, {%8,%9}, {%0,%1,%2,%3};\n"
        : "+f"(d[0]), "+f"(d[1]), "+f"(d[2]), "+f"(d[3])
        : "r"(a[0]), "r"(a[1]), "r"(a[2]), "r"(a[3]), "r"(b[0]), "r"(b[1]));
}

__device__ __forceinline__ void cvt_hilo(float x, __nv_bfloat16& h, __nv_bfloat16& l) {
    h = __float2bfloat16(x);
    l = __float2bfloat16(x - __bfloat162float(h));
}

// ---------------- Kernel 1: QKV GEMM via bf16 hi/lo split (R12-proven version) ----------------
__global__ __launch_bounds__(256) void gemm_kernel(
    const float* __restrict__ X, const float* __restrict__ W)
{
    __shared__ __nv_bfloat16 Xh[32][XSTR], Xl[32][XSTR];
    __shared__ __nv_bfloat16 Wh[NTILE][XSTR], Wl[NTILE][XSTR];

    const int tid = threadIdx.x;
    const int warp = tid >> 5, lane = tid & 31;
    const int wm = warp & 1, wn = warp >> 1;
    const int o0 = blockIdx.x * NTILE;
    const int k0 = blockIdx.y * KPER;

    float d[4][4];
#pragma unroll
    for (int i = 0; i < 4; i++)
#pragma unroll
        for (int j = 0; j < 4; j++) d[i][j] = 0.f;

    const int a_row = wm * 16 + (lane & 7) + ((lane & 8) ? 8 : 0);
    const int a_ks  = (lane & 16) ? 8 : 0;
    const int b_row0 = wn * 32 + (lane & 7) + ((lane & 16) ? 8 : 0);
    const int b_ks  = (lane & 8) ? 8 : 0;

    for (int kc = 0; kc < KPER; kc += KCH) {
        {
            int r = tid >> 3, c4 = (tid & 7) * 4;
            float4 v = *(const float4*)&X[(size_t)r * HIDDEN_ + k0 + kc + c4];
            cvt_hilo(v.x, Xh[r][c4+0], Xl[r][c4+0]);
            cvt_hilo(v.y, Xh[r][c4+1], Xl[r][c4+1]);
            cvt_hilo(v.z, Xh[r][c4+2], Xl[r][c4+2]);
            cvt_hilo(v.w, Xh[r][c4+3], Xl[r][c4+3]);
        }
        {
            int o = tid >> 1;
            int base = (tid & 1) * 16;
            const float4* src = (const float4*)&W[(size_t)(o0 + o) * HIDDEN_ + k0 + kc + base];
#pragma unroll
            for (int i = 0; i < 4; i++) {
                float4 v = src[i];
                int kk = base + i * 4;
                cvt_hilo(v.x, Wh[o][kk+0], Wl[o][kk+0]);
                cvt_hilo(v.y, Wh[o][kk+1], Wl[o][kk+1]);
                cvt_hilo(v.z, Wh[o][kk+2], Wl[o][kk+2]);
                cvt_hilo(v.w, Wh[o][kk+3], Wl[o][kk+3]);
            }
        }
        __syncthreads();

#pragma unroll
        for (int ks = 0; ks < 2; ks++) {
            const int kk = ks * 16;
            uint32_t ah[4], al[4];
            ldsm4(ah, smem_u32(&Xh[a_row][kk + a_ks]));
            ldsm4(al, smem_u32(&Xl[a_row][kk + a_ks]));
            uint32_t bh[8], bl[8];
            ldsm4(bh + 0, smem_u32(&Wh[b_row0][kk + b_ks]));
            ldsm4(bh + 4, smem_u32(&Wh[b_row0 + 16][kk + b_ks]));
            ldsm4(bl + 0, smem_u32(&Wl[b_row0][kk + b_ks]));
            ldsm4(bl + 4, smem_u32(&Wl[b_row0 + 16][kk + b_ks]));
#pragma unroll
            for (int nt = 0; nt < 4; nt++) {
                uint32_t* Bh = bh + nt * 2;
                uint32_t* Bl = bl + nt * 2;
                mma_bf16(d[nt], ah, Bh);
                mma_bf16(d[nt], ah, Bl);
                mma_bf16(d[nt], al, Bh);
            }
        }
        __syncthreads();
    }

    const int g = lane >> 2, t2 = (lane & 3) * 2;
    const int ksb = blockIdx.y * B_;
#pragma unroll
    for (int nt = 0; nt < 4; nt++) {
        int o = o0 + wn * 32 + nt * 8 + t2;
        int b0 = wm * 16 + g;
        float* dst0 = &g_part[(size_t)(ksb + b0) * QKV_OUT_ + o];
        dst0[0] = d[nt][0]; dst0[1] = d[nt][1];
        float* dst1 = &g_part[(size_t)(ksb + b0 + 8) * QKV_OUT_ + o];
        dst1[0] = d[nt][2]; dst1[1] = d[nt][3];
    }
}

// ---------------- Kernel 2: split-K reduce + bias + scatter ----------------
__global__ __launch_bounds__(256) void gemm_reduce_kernel(
    const float* __restrict__ bias, float* __restrict__ out)
{
    int i = blockIdx.x * 256 + threadIdx.x;
    if (i >= B_ * QKV_OUT_) return;
    int b = i / QKV_OUT_, o = i - b * QKV_OUT_;
    float s = bias[o];
#pragma unroll
    for (int ks = 0; ks < KSPLIT; ks++)
        s += g_part[(size_t)(ks * B_ + b) * QKV_OUT_ + o];
    if (o < QD) {
        g_q[b * QD + o] = s;
    } else if (o < QD + KD) {
        int r = o - QD;
        out[OFF_K + ((size_t)b * T_TOT + PAST) * KD + r] = s;
    } else {
        int r = o - QD - KD;
        out[OFF_V + ((size_t)b * T_TOT + PAST) * KD + r] = s;
    }
}

// ---------------- Kernel 3: fused cache-copy + split-KV flash attention ----------------
// Chunks 0..7: branch-free hot loop (all tokens < PAST), 2 tokens/iter (MLP=4),
// streaming __ldcs/__stcs. Chunk 8: single new token, warp 0 only.
__global__ __launch_bounds__(256) void attn_kernel(
    const float* __restrict__ Kc, const float* __restrict__ Vc,
    const float* __restrict__ mask, float* __restrict__ out)
{
    const int ch = blockIdx.x, kv = blockIdx.y, b = blockIdx.z;
    const int w = threadIdx.x >> 5, lane = threadIdx.x & 31;

    float4 q[NREP];
#pragma unroll
    for (int h = 0; h < NREP; h++)
        q[h] = *(const float4*)&g_q[(size_t)b * QD + (kv * NREP + h) * HDIM + lane * 4];

    float m[NREP], l[NREP];
    float4 acc[NREP];
#pragma unroll
    for (int h = 0; h < NREP; h++) {
        m[h] = -1e30f; l[h] = 0.f;
        acc[h] = make_float4(0.f, 0.f, 0.f, 0.f);
    }

    if (ch < 8) {
        const int t0 = ch * TCHUNK + w * 32;
        const size_t tstride = (size_t)NKV * HDIM;     // token stride (both src & dst inner layout)
#pragma unroll 1
        for (int j = 0; j < 32; j += 2) {
            const int t = t0 + j;
            const size_t s0 = (((size_t)b * PAST + t) * NKV + kv) * HDIM;
            const size_t d0 = (((size_t)b * T_TOT + t) * NKV + kv) * HDIM;

            // ---- 4 loads up front (MLP=4) ----
            float4 kA = __ldcs(((const float4*)(Kc + s0)) + lane);
            float4 vA = __ldcs(((const float4*)(Vc + s0)) + lane);
            float4 kB = __ldcs(((const float4*)(Kc + s0 + tstride)) + lane);
            float4 vB = __ldcs(((const float4*)(Vc + s0 + tstride)) + lane);
            float mka = __ldg(&mask[(size_t)b * T_TOT + t]);
            float mkb = __ldg(&mask[(size_t)b * T_TOT + t + 1]);

            // ---- fused cache copy (streaming stores) ----
            __stcs(((float4*)(out + OFF_K + d0)) + lane, kA);
            __stcs(((float4*)(out + OFF_V + d0)) + lane, vA);
            __stcs(((float4*)(out + OFF_K + d0 + tstride)) + lane, kB);
            __stcs(((float4*)(out + OFF_V + d0 + tstride)) + lane, vB);

            // ---- scores ----
            float sA[NREP], sB[NREP];
#pragma unroll
            for (int h = 0; h < NREP; h++) {
                sA[h] = q[h].x * kA.x + q[h].y * kA.y + q[h].z * kA.z + q[h].w * kA.w;
                sB[h] = q[h].x * kB.x + q[h].y * kB.y + q[h].z * kB.z + q[h].w * kB.w;
            }
#pragma unroll
            for (int off = 16; off; off >>= 1) {
#pragma unroll
                for (int h = 0; h < NREP; h++) {
                    sA[h] += __shfl_xor_sync(0xFFFFFFFFu, sA[h], off);
                    sB[h] += __shfl_xor_sync(0xFFFFFFFFu, sB[h], off);
                }
            }

            // ---- combined 2-token online-softmax update ----
#pragma unroll
            for (int h = 0; h < NREP; h++) {
                float svA = sA[h] * SCALE_ + mka;
                float svB = sB[h] * SCALE_ + mkb;
                float mn = fmaxf(m[h], fmaxf(svA, svB));
                float corr = __expf(m[h] - mn);
                float pA = __expf(svA - mn);
                float pB = __expf(svB - mn);
                l[h] = l[h] * corr + pA + pB;
                acc[h].x = acc[h].x * corr + pA * vA.x + pB * vB.x;
                acc[h].y = acc[h].y * corr + pA * vA.y + pB * vB.y;
                acc[h].z = acc[h].z * corr + pA * vA.z + pB * vB.z;
                acc[h].w = acc[h].w * corr + pA * vA.w + pB * vB.w;
                m[h] = mn;
            }
        }
    } else if (w == 0) {
        // single new token t = PAST (written to out by gemm_reduce)
        const int t = PAST;
        const size_t d0 = (((size_t)b * T_TOT + t) * NKV + kv) * HDIM;
        float4 k4 = __ldg(((const float4*)(out + OFF_K + d0)) + lane);
        float4 v4 = __ldg(((const float4*)(out + OFF_V + d0)) + lane);
        float mk = __ldg(&mask[(size_t)b * T_TOT + t]);
        float s[NREP];
#pragma unroll
        for (int h = 0; h < NREP; h++)
            s[h] = q[h].x * k4.x + q[h].y * k4.y + q[h].z * k4.z + q[h].w * k4.w;
#pragma unroll
        for (int off = 16; off; off >>= 1)
#pragma unroll
            for (int h = 0; h < NREP; h++)
                s[h] += __shfl_xor_sync(0xFFFFFFFFu, s[h], off);
#pragma unroll
        for (int h = 0; h < NREP; h++) {
            float sv = s[h] * SCALE_ + mk;
            m[h] = sv; l[h] = 1.f;
            acc[h] = make_float4(v4.x, v4.y, v4.z, v4.w);
        }
    }

    __shared__ float sm_m[8][NREP];
    __shared__ float sm_l[8][NREP];
    __shared__ float sm_acc[8][NREP][HDIM];
    if (lane < NREP) { sm_m[w][lane] = m[lane]; sm_l[w][lane] = l[lane]; }
#pragma unroll
    for (int h = 0; h < NREP; h++)
        *(float4*)&sm_acc[w][h][lane * 4] = acc[h];
    __syncthreads();

    const int base = ((b * NKV + kv) * NCHUNK + ch) * NREP;
    for (int e = threadIdx.x; e < NREP * HDIM; e += 256) {
        int h = e >> 7, dd = e & 127;
        float M = sm_m[0][h];
#pragma unroll
        for (int ww = 1; ww < 8; ww++) M = fmaxf(M, sm_m[ww][h]);
        float a = 0.f;
#pragma unroll
        for (int ww = 0; ww < 8; ww++)
            a += sm_acc[ww][h][dd] * __expf(sm_m[ww][h] - M);
        g_pacc[(size_t)(base + h) * HDIM + dd] = a;
    }
    if (threadIdx.x < NREP) {
        int h = threadIdx.x;
        float M = sm_m[0][h];
#pragma unroll
        for (int ww = 1; ww < 8; ww++) M = fmaxf(M, sm_m[ww][h]);
        float L = 0.f;
#pragma unroll
        for (int ww = 0; ww < 8; ww++)
            L += sm_l[ww][h] * __expf(sm_m[ww][h] - M);
        g_pm[base + h] = M;
        g_pl[base + h] = L;
    }
}

// ---------------- Kernel 4: cross-chunk softmax reduce ----------------
__global__ __launch_bounds__(128) void attn_final_kernel(float* __restrict__ out)
{
    const int h = blockIdx.x, b = blockIdx.y, d = threadIdx.x;
    const int kv = h >> 2, hh = h & 3;
    const int base0 = (b * NKV + kv) * NCHUNK;
    float M = -1e30f;
#pragma unroll
    for (int ch = 0; ch < NCHUNK; ch++)
        M = fmaxf(M, g_pm[(base0 + ch) * NREP + hh]);
    float L = 0.f, A = 0.f;
#pragma unroll
    for (int ch = 0; ch < NCHUNK; ch++) {
        int idx = (base0 + ch) * NREP + hh;
        float f = __expf(g_pm[idx] - M);
        L += g_pl[idx] * f;
        A += g_pacc[(size_t)idx * HDIM + d] * f;
    }
    out[OFF_OUT + ((size_t)b * NHEAD + h) * HDIM + d] = A / L;
}

// ---------------- launch ----------------
extern "C" void kernel_launch(void* const* d_in, const int* in_sizes, int n_in,
                              void* d_out, int out_size)
{
    const float* input_t = (const float*)d_in[0];
    const float* key_cache = (const float*)d_in[1];
    const float* value_cache = (const float*)d_in[2];
    const float* attention_mask = (const float*)d_in[4];
    const float* W_qkv = (const float*)d_in[6];
    const float* b_qkv = (const float*)d_in[7];
    float* out = (float*)d_out;

    gemm_kernel<<<dim3(QKV_OUT_ / NTILE, KSPLIT), 256>>>(input_t, W_qkv);
    gemm_reduce_kernel<<<(B_ * QKV_OUT_ + 255) / 256, 256>>>(b_qkv, out);
    attn_kernel<<<dim3(NCHUNK, NKV, B_), 256>>>(key_cache, value_cache, attention_mask, out);
    attn_final_kernel<<<dim3(NHEAD, B_), 128>>>(out);
}

// round 15
// speedup vs baseline: 1.0452x; 1.0037x over previous
#include <cuda_runtime.h>
#include <cuda_bf16.h>
#include <cstdint>

// Problem constants
#define B_      32
#define NHEAD   32
#define NKV     8
#define NREP    4
#define HDIM    128
#define HIDDEN_ 4096
#define QKV_OUT_ 6144          // (8*2+32)*128
#define QD      4096           // NHEAD*HDIM
#define KD      1024           // NKV*HDIM
#define PAST    2048
#define T_TOT   2049           // PAST + 1
#define SCALE_  0.08838834764831845f  // 1/sqrt(128)

// d_out layout: [out (32*32*128)] [k_cat (32*2049*8*128)] [v_cat (...)]
#define OFF_OUT 0
#define SZ_OUT  (B_*NHEAD*HDIM)
#define OFF_K   (SZ_OUT)
#define SZ_KC   ((size_t)B_*T_TOT*NKV*HDIM)
#define OFF_V   (OFF_K + SZ_KC)

// GEMM split-K
#define KSPLIT  8
#define KPER    (HIDDEN_/KSPLIT)                // 512
#define KCH     32
#define NTILE   128
#define XSTR    40

// attention chunking
#define TCHUNK  256
#define NCHUNK  9

// ---------------- scratch ----------------
__device__ float g_part[KSPLIT * B_ * QKV_OUT_];
__device__ float g_q[B_ * QD];
__device__ float g_pm[B_ * NKV * NCHUNK * NREP];
__device__ float g_pl[B_ * NKV * NCHUNK * NREP];
__device__ float g_pacc[B_ * NKV * NCHUNK * NREP * HDIM];

// ---------------- tensor-core helpers ----------------
__device__ __forceinline__ uint32_t smem_u32(const void* p) {
    return (uint32_t)__cvta_generic_to_shared(p);
}

__device__ __forceinline__ void ldsm4(uint32_t* r, uint32_t addr) {
    asm volatile("ldmatrix.sync.aligned.m8n8.x4.shared.b16 {%0,%1,%2,%3}, [%4];\n"
                 : "=r"(r[0]), "=r"(r[1]), "=r"(r[2]), "=r"(r[3]) : "r"(addr));
}

__device__ __forceinline__ void mma_bf16(float* d, const uint32_t* a, const uint32_t* b) {
    asm volatile(
        "mma.sync.aligned.m16n8k16.row.col.f32.bf16.bf16.f32 "
        "{%0,%1,%2,%3}, {%4,%5,%6,%7}, {%8,%9}, {%0,%1,%2,%3};\n"
        : "+f"(d[0]), "+f"(d[1]), "+f"(d[2]), "+f"(d[3])
        : "r"(a[0]), "r"(a[1]), "r"(a[2]), "r"(a[3]), "r"(b[0]), "r"(b[1]));
}

__device__ __forceinline__ void cvt_hilo(float x, __nv_bfloat16& h, __nv_bfloat16& l) {
    h = __float2bfloat16(x);
    l = __float2bfloat16(x - __bfloat162float(h));
}

// ---------------- Kernel 1: QKV GEMM (bf16 hi/lo, register-prefetched mainloop) ----------------
__global__ __launch_bounds__(256) void gemm_kernel(
    const float* __restrict__ X, const float* __restrict__ W)
{
    __shared__ __nv_bfloat16 Xh[32][XSTR], Xl[32][XSTR];
    __shared__ __nv_bfloat16 Wh[NTILE][XSTR], Wl[NTILE][XSTR];

    const int tid = threadIdx.x;
    const int warp = tid >> 5, lane = tid & 31;
    const int wm = warp & 1, wn = warp >> 1;
    const int o0 = blockIdx.x * NTILE;
    const int k0 = blockIdx.y * KPER;

    float d[4][4];
#pragma unroll
    for (int i = 0; i < 4; i++)
#pragma unroll
        for (int j = 0; j < 4; j++) d[i][j] = 0.f;

    const int a_row = wm * 16 + (lane & 7) + ((lane & 8) ? 8 : 0);
    const int a_ks  = (lane & 16) ? 8 : 0;
    const int b_row0 = wn * 32 + (lane & 7) + ((lane & 16) ? 8 : 0);
    const int b_ks  = (lane & 8) ? 8 : 0;

    // per-thread load coordinates
    const int xr = tid >> 3, xc4 = (tid & 7) * 4;
    const int wo = tid >> 1, wbase = (tid & 1) * 16;
    const float* Xp = &X[(size_t)xr * HIDDEN_ + k0 + xc4];
    const float* Wp = &W[(size_t)(o0 + wo) * HIDDEN_ + k0 + wbase];

    // prologue: fetch tile 0 into registers
    float4 xv = *(const float4*)Xp;
    float4 wv[4];
#pragma unroll
    for (int i = 0; i < 4; i++) wv[i] = ((const float4*)Wp)[i];

    for (int kc = 0; kc < KPER; kc += KCH) {
        // convert current registers -> smem
        cvt_hilo(xv.x, Xh[xr][xc4+0], Xl[xr][xc4+0]);
        cvt_hilo(xv.y, Xh[xr][xc4+1], Xl[xr][xc4+1]);
        cvt_hilo(xv.z, Xh[xr][xc4+2], Xl[xr][xc4+2]);
        cvt_hilo(xv.w, Xh[xr][xc4+3], Xl[xr][xc4+3]);
#pragma unroll
        for (int i = 0; i < 4; i++) {
            int kk = wbase + i * 4;
            cvt_hilo(wv[i].x, Wh[wo][kk+0], Wl[wo][kk+0]);
            cvt_hilo(wv[i].y, Wh[wo][kk+1], Wl[wo][kk+1]);
            cvt_hilo(wv[i].z, Wh[wo][kk+2], Wl[wo][kk+2]);
            cvt_hilo(wv[i].w, Wh[wo][kk+3], Wl[wo][kk+3]);
        }
        __syncthreads();

        // prefetch next tile into registers (overlaps with ldsm+mma below)
        {
            int kn = (kc + KCH < KPER) ? (kc + KCH) : kc;
            xv = *(const float4*)(Xp + kn);
#pragma unroll
            for (int i = 0; i < 4; i++) wv[i] = ((const float4*)(Wp + kn))[i];
        }

#pragma unroll
        for (int ks = 0; ks < 2; ks++) {
            const int kk = ks * 16;
            uint32_t ah[4], al[4];
            ldsm4(ah, smem_u32(&Xh[a_row][kk + a_ks]));
            ldsm4(al, smem_u32(&Xl[a_row][kk + a_ks]));
            uint32_t bh[8], bl[8];
            ldsm4(bh + 0, smem_u32(&Wh[b_row0][kk + b_ks]));
            ldsm4(bh + 4, smem_u32(&Wh[b_row0 + 16][kk + b_ks]));
            ldsm4(bl + 0, smem_u32(&Wl[b_row0][kk + b_ks]));
            ldsm4(bl + 4, smem_u32(&Wl[b_row0 + 16][kk + b_ks]));
#pragma unroll
            for (int nt = 0; nt < 4; nt++) {
                uint32_t* Bh = bh + nt * 2;
                uint32_t* Bl = bl + nt * 2;
                mma_bf16(d[nt], ah, Bh);
                mma_bf16(d[nt], ah, Bl);
                mma_bf16(d[nt], al, Bh);
            }
        }
        __syncthreads();
    }

    const int g = lane >> 2, t2 = (lane & 3) * 2;
    const int ksb = blockIdx.y * B_;
#pragma unroll
    for (int nt = 0; nt < 4; nt++) {
        int o = o0 + wn * 32 + nt * 8 + t2;
        int b0 = wm * 16 + g;
        float* dst0 = &g_part[(size_t)(ksb + b0) * QKV_OUT_ + o];
        dst0[0] = d[nt][0]; dst0[1] = d[nt][1];
        float* dst1 = &g_part[(size_t)(ksb + b0 + 8) * QKV_OUT_ + o];
        dst1[0] = d[nt][2]; dst1[1] = d[nt][3];
    }
}

// ---------------- Kernel 2: split-K reduce + bias + scatter ----------------
__global__ __launch_bounds__(256) void gemm_reduce_kernel(
    const float* __restrict__ bias, float* __restrict__ out)
{
    int i = blockIdx.x * 256 + threadIdx.x;
    if (i >= B_ * QKV_OUT_) return;
    int b = i / QKV_OUT_, o = i - b * QKV_OUT_;
    float s = bias[o];
#pragma unroll
    for (int ks = 0; ks < KSPLIT; ks++)
        s += g_part[(size_t)(ks * B_ + b) * QKV_OUT_ + o];
    if (o < QD) {
        g_q[b * QD + o] = s;
    } else if (o < QD + KD) {
        int r = o - QD;
        out[OFF_K + ((size_t)b * T_TOT + PAST) * KD + r] = s;
    } else {
        int r = o - QD - KD;
        out[OFF_V + ((size_t)b * T_TOT + PAST) * KD + r] = s;
    }
}

// ---------------- Kernel 3: fused cache-copy + split-KV flash attention (R12-proven) ----------------
// 2 tokens per iteration: MLP=4 on the streamed loads, one softmax-corr per pair.
// __ldcs/__stcs: K/V touched exactly once -> keep it out of L2's working set.
__global__ __launch_bounds__(256) void attn_kernel(
    const float* __restrict__ Kc, const float* __restrict__ Vc,
    const float* __restrict__ mask, float* __restrict__ out)
{
    const int ch = blockIdx.x, kv = blockIdx.y, b = blockIdx.z;
    const int w = threadIdx.x >> 5, lane = threadIdx.x & 31;

    float4 q[NREP];
#pragma unroll
    for (int h = 0; h < NREP; h++)
        q[h] = *(const float4*)&g_q[(size_t)b * QD + (kv * NREP + h) * HDIM + lane * 4];

    float m[NREP], l[NREP];
    float4 acc[NREP];
#pragma unroll
    for (int h = 0; h < NREP; h++) {
        m[h] = -1e30f; l[h] = 0.f;
        acc[h] = make_float4(0.f, 0.f, 0.f, 0.f);
    }

    const int t0 = ch * TCHUNK + w * 32;
#pragma unroll 1
    for (int j = 0; j < 32; j += 2) {
        const int ta = t0 + j;
        if (ta >= T_TOT) break;
        const int tb = ta + 1;
        const bool bok = (tb < T_TOT);

        const size_t da = (((size_t)b * T_TOT + ta) * NKV + kv) * HDIM;
        const size_t db = da + (size_t)NKV * HDIM;

        float4 kA, vA, kB, vB;
        // ---- issue all 4 loads up front (MLP=4) ----
        if (ta < PAST) {
            size_t sa = (((size_t)b * PAST + ta) * NKV + kv) * HDIM;
            kA = __ldcs(((const float4*)(Kc + sa)) + lane);
            vA = __ldcs(((const float4*)(Vc + sa)) + lane);
        } else {
            kA = __ldg(((const float4*)(out + OFF_K + da)) + lane);
            vA = __ldg(((const float4*)(out + OFF_V + da)) + lane);
        }
        if (bok) {
            if (tb < PAST) {
                size_t sb = (((size_t)b * PAST + tb) * NKV + kv) * HDIM;
                kB = __ldcs(((const float4*)(Kc + sb)) + lane);
                vB = __ldcs(((const float4*)(Vc + sb)) + lane);
            } else {
                kB = __ldg(((const float4*)(out + OFF_K + db)) + lane);
                vB = __ldg(((const float4*)(out + OFF_V + db)) + lane);
            }
        } else {
            kB = make_float4(0.f, 0.f, 0.f, 0.f);
            vB = make_float4(0.f, 0.f, 0.f, 0.f);
        }
        float mka = __ldg(&mask[(size_t)b * T_TOT + ta]);
        float mkb = bok ? __ldg(&mask[(size_t)b * T_TOT + tb]) : 0.f;

        // ---- fused cache copy (streaming stores) ----
        if (ta < PAST) {
            __stcs(((float4*)(out + OFF_K + da)) + lane, kA);
            __stcs(((float4*)(out + OFF_V + da)) + lane, vA);
        }
        if (bok && tb < PAST) {
            __stcs(((float4*)(out + OFF_K + db)) + lane, kB);
            __stcs(((float4*)(out + OFF_V + db)) + lane, vB);
        }

        // ---- scores ----
        float sA[NREP], sB[NREP];
#pragma unroll
        for (int h = 0; h < NREP; h++) {
            sA[h] = q[h].x * kA.x + q[h].y * kA.y + q[h].z * kA.z + q[h].w * kA.w;
            sB[h] = q[h].x * kB.x + q[h].y * kB.y + q[h].z * kB.z + q[h].w * kB.w;
        }
#pragma unroll
        for (int off = 16; off; off >>= 1) {
#pragma unroll
            for (int h = 0; h < NREP; h++) {
                sA[h] += __shfl_xor_sync(0xFFFFFFFFu, sA[h], off);
                sB[h] += __shfl_xor_sync(0xFFFFFFFFu, sB[h], off);
            }
        }

        // ---- combined 2-token online-softmax update ----
#pragma unroll
        for (int h = 0; h < NREP; h++) {
            float svA = sA[h] * SCALE_ + mka;
            float svB = bok ? (sB[h] * SCALE_ + mkb) : -1e30f;
            float mn = fmaxf(m[h], fmaxf(svA, svB));
            float corr = __expf(m[h] - mn);
            float pA = __expf(svA - mn);
            float pB = __expf(svB - mn);
            l[h] = l[h] * corr + pA + pB;
            acc[h].x = acc[h].x * corr + pA * vA.x + pB * vB.x;
            acc[h].y = acc[h].y * corr + pA * vA.y + pB * vB.y;
            acc[h].z = acc[h].z * corr + pA * vA.z + pB * vB.z;
            acc[h].w = acc[h].w * corr + pA * vA.w + pB * vB.w;
            m[h] = mn;
        }
    }

    __shared__ float sm_m[8][NREP];
    __shared__ float sm_l[8][NREP];
    __shared__ float sm_acc[8][NREP][HDIM];
    if (lane < NREP) { sm_m[w][lane] = m[lane]; sm_l[w][lane] = l[lane]; }
#pragma unroll
    for (int h = 0; h < NREP; h++)
        *(float4*)&sm_acc[w][h][lane * 4] = acc[h];
    __syncthreads();

    const int base = ((b * NKV + kv) * NCHUNK + ch) * NREP;
    for (int e = threadIdx.x; e < NREP * HDIM; e += 256) {
        int h = e >> 7, dd = e & 127;
        float M = sm_m[0][h];
#pragma unroll
        for (int ww = 1; ww < 8; ww++) M = fmaxf(M, sm_m[ww][h]);
        float a = 0.f;
#pragma unroll
        for (int ww = 0; ww < 8; ww++)
            a += sm_acc[ww][h][dd] * __expf(sm_m[ww][h] - M);
        g_pacc[(size_t)(base + h) * HDIM + dd] = a;
    }
    if (threadIdx.x < NREP) {
        int h = threadIdx.x;
        float M = sm_m[0][h];
#pragma unroll
        for (int ww = 1; ww < 8; ww++) M = fmaxf(M, sm_m[ww][h]);
        float L = 0.f;
#pragma unroll
        for (int ww = 0; ww < 8; ww++)
            L += sm_l[ww][h] * __expf(sm_m[ww][h] - M);
        g_pm[base + h] = M;
        g_pl[base + h] = L;
    }
}

// ---------------- Kernel 4: cross-chunk softmax reduce ----------------
__global__ __launch_bounds__(128) void attn_final_kernel(float* __restrict__ out)
{
    const int h = blockIdx.x, b = blockIdx.y, d = threadIdx.x;
    const int kv = h >> 2, hh = h & 3;
    const int base0 = (b * NKV + kv) * NCHUNK;
    float M = -1e30f;
#pragma unroll
    for (int ch = 0; ch < NCHUNK; ch++)
        M = fmaxf(M, g_pm[(base0 + ch) * NREP + hh]);
    float L = 0.f, A = 0.f;
#pragma unroll
    for (int ch = 0; ch < NCHUNK; ch++) {
        int idx = (base0 + ch) * NREP + hh;
        float f = __expf(g_pm[idx] - M);
        L += g_pl[idx] * f;
        A += g_pacc[(size_t)idx * HDIM + d] * f;
    }
    out[OFF_OUT + ((size_t)b * NHEAD + h) * HDIM + d] = A / L;
}

// ---------------- launch ----------------
extern "C" void kernel_launch(void* const* d_in, const int* in_sizes, int n_in,
                              void* d_out, int out_size)
{
    const float* input_t = (const float*)d_in[0];
    const float* key_cache = (const float*)d_in[1];
    const float* value_cache = (const float*)d_in[2];
    const float* attention_mask = (const float*)d_in[4];
    const float* W_qkv = (const float*)d_in[6];
    const float* b_qkv = (const float*)d_in[7];
    float* out = (float*)d_out;

    gemm_kernel<<<dim3(QKV_OUT_ / NTILE, KSPLIT), 256>>>(input_t, W_qkv);
    gemm_reduce_kernel<<<(B_ * QKV_OUT_ + 255) / 256, 256>>>(b_qkv, out);
    attn_kernel<<<dim3(NCHUNK, NKV, B_), 256>>>(key_cache, value_cache, attention_mask, out);
    attn_final_kernel<<<dim3(NHEAD, B_), 128>>>(out);
}